// round 2
// baseline (speedup 1.0000x reference)
#include <cuda_runtime.h>
#include <cuda_fp16.h>
#include <cstdint>
#include <cstddef>

// ============================================================================
// Mex forward: y[n,i] = log( sum_k exp(P[n,k]) * exp(O[i,k]) ) - log(K)
//   N = 65536 pixels (b,oh,ow), I = 256 instances, K = 576 (c,fh,fw)
// pass0: exp(offsets) -> fp16 B ; pass1: im2col+exp -> fp16 A ;
// pass2: mma.sync fp16 GEMM (fp32 accum) + log epilogue (base sm_103 target:
//        tcgen05 is unavailable, ptxas rejects it -> classic HMMA path)
// ============================================================================

#define DINL __device__ __forceinline__

static constexpr int BB   = 64;
static constexpr int CC   = 64;
static constexpr int HH   = 64;
static constexpr int WW   = 64;
static constexpr int OH   = 32;
static constexpr int NI   = 256;
static constexpr int KTOT = 576;           // 64*3*3
static constexpr int NPIX = BB * OH * 32;  // 65536
static constexpr int MTILE  = 128;
static constexpr int NTILE  = 128;
static constexpr int KCHUNK = 64;          // 128B rows (SW128 pattern)
static constexpr int NCHUNK = KTOT / KCHUNK;  // 9
static constexpr float LOG_K = 6.3561076606958915f;  // ln(576)

// scratch (device globals: no runtime allocation allowed)
__device__ __half g_A[(size_t)NPIX * KTOT];   // ~75.5 MB
__device__ __half g_B[(size_t)NI * KTOT];     // 288 KB

// ---------------------------------------------------------------------------
// helpers
// ---------------------------------------------------------------------------
DINL uint32_t smem_u32(const void* p) {
    uint32_t a;
    asm("{ .reg .u64 t; cvta.to.shared.u64 t, %1; cvt.u32.u64 %0, t; }"
        : "=r"(a) : "l"(p));
    return a;
}
DINL void cp_async16(uint32_t smem_addr, const void* gptr) {
    asm volatile("cp.async.cg.shared.global [%0], [%1], 16;"
                 :: "r"(smem_addr), "l"(gptr) : "memory");
}
DINL void cp_commit() { asm volatile("cp.async.commit_group;" ::: "memory"); }
template <int N> DINL void cp_wait() {
    asm volatile("cp.async.wait_group %0;" :: "n"(N) : "memory");
}
DINL void ldm_x4(uint32_t addr, uint32_t& r0, uint32_t& r1,
                 uint32_t& r2, uint32_t& r3) {
    asm volatile("ldmatrix.sync.aligned.m8n8.x4.shared.b16 {%0,%1,%2,%3}, [%4];"
                 : "=r"(r0), "=r"(r1), "=r"(r2), "=r"(r3) : "r"(addr));
}
DINL void mma16816(float* c, const uint32_t* a, uint32_t b0, uint32_t b1) {
    asm volatile(
        "mma.sync.aligned.m16n8k16.row.col.f32.f16.f16.f32 "
        "{%0,%1,%2,%3}, {%4,%5,%6,%7}, {%8,%9}, {%0,%1,%2,%3};"
        : "+f"(c[0]), "+f"(c[1]), "+f"(c[2]), "+f"(c[3])
        : "r"(a[0]), "r"(a[1]), "r"(a[2]), "r"(a[3]), "r"(b0), "r"(b1));
}
DINL uint32_t sw128(uint32_t off) { return off ^ ((off >> 3) & 0x70); }

// ---------------------------------------------------------------------------
// pass0: B[i,k] = fp16(exp(offsets[i,k]))
// ---------------------------------------------------------------------------
__global__ void mex_pass0(const float* __restrict__ offs, __half* __restrict__ Bm) {
    int i = blockIdx.x * blockDim.x + threadIdx.x;
    if (i < NI * KTOT) Bm[i] = __float2half_rn(__expf(offs[i]));
}

// ---------------------------------------------------------------------------
// pass1: im2col + exp.  One CTA per (b, oh).  A[n, k], n = bo*32 + ow,
// k = c*9 + fh*3 + fw, value = exp(x[b,c,2*oh-1+fh,2*ow-1+fw]) (pad -> 1.0)
// ---------------------------------------------------------------------------
__global__ void __launch_bounds__(256) mex_pass1(const float* __restrict__ x,
                                                 __half* __restrict__ A) {
    __shared__ __half xs[CC * 3 * 66];  // [c][fh][iw+1]
    const int bo  = blockIdx.x;         // b*32 + oh
    const int b   = bo >> 5;
    const int oh  = bo & 31;
    const int tid = threadIdx.x;
    const float* xb = x + (size_t)b * (CC * HH * WW);

    for (int idx = tid; idx < CC * 3 * 66; idx += 256) {
        int c  = idx / 198;
        int rr = idx - c * 198;
        int fh = rr / 66;
        int w  = rr - fh * 66 - 1;          // iw in [-1, 64]
        int ih = oh * 2 - 1 + fh;
        bool ok = (ih >= 0) & (ih < HH) & (w >= 0) & (w < WW);
        float v = ok ? xb[((c << 6) + ih) * 64 + w] : 0.0f;
        xs[idx] = __float2half_rn(ok ? __expf(v) : 1.0f);
    }
    __syncthreads();

    __half* Ab = A + (size_t)bo * (32 * KTOT);
#pragma unroll
    for (int it = 0; it < 9; it++) {
        int l  = (it * 256 + tid) * 8;      // 8 consecutive k (576 % 8 == 0)
        int ow = l / KTOT;
        int k0 = l - ow * KTOT;
        __align__(16) __half tmp[8];
#pragma unroll
        for (int j = 0; j < 8; j++) {
            int k  = k0 + j;
            int c  = k / 9;
            int r9 = k - c * 9;
            int fh = r9 / 3;
            int fw = r9 - fh * 3;
            tmp[j] = xs[(c * 3 + fh) * 66 + ow * 2 + fw];
        }
        *reinterpret_cast<uint4*>(Ab + l) = *reinterpret_cast<const uint4*>(tmp);
    }
}

// ---------------------------------------------------------------------------
// pass2: GEMM via mma.sync.  CTA tile 128x128, 8 warps (2M x 4N), warp 64x32,
// K-chunk 64, SW128-swizzled smem, double-buffered cp.async.
// grid = (2, 512): x = N-split (so both halves of an A tile hit L2), y = M tile.
// ---------------------------------------------------------------------------
static constexpr int STAGE_BYTES = 128 * 128;  // 16 KB per operand per stage
static constexpr int A0_OFF = 0;
static constexpr int A1_OFF = STAGE_BYTES;
static constexpr int B0_OFF = 2 * STAGE_BYTES;
static constexpr int B1_OFF = 3 * STAGE_BYTES;
static constexpr int SMEM_BYTES = 4 * STAGE_BYTES + 128;  // + align slack

DINL void load_chunk(uint32_t a_s, uint32_t b_s, int tid,
                     const __half* Abase, const __half* Bbase, int kc) {
    const __half* ap = Abase + kc * KCHUNK;
    const __half* bp = Bbase + kc * KCHUNK;
#pragma unroll
    for (int i = 0; i < 4; i++) {            // A: 128 rows x 8 x 16B
        int idx = tid + i * 256;
        int row = idx >> 3, ch = idx & 7;
        uint32_t off = (uint32_t)(row * 128 + ch * 16);
        cp_async16(a_s + sw128(off), ap + (size_t)row * KTOT + ch * 8);
    }
#pragma unroll
    for (int i = 0; i < 4; i++) {            // B: 128 rows x 8 x 16B
        int idx = tid + i * 256;
        int row = idx >> 3, ch = idx & 7;
        uint32_t off = (uint32_t)(row * 128 + ch * 16);
        cp_async16(b_s + sw128(off), bp + (size_t)row * KTOT + ch * 8);
    }
}

__global__ void __launch_bounds__(256, 2) mex_gemm(const __half* __restrict__ Ag,
                                                   const __half* __restrict__ Bg,
                                                   float* __restrict__ out) {
    extern __shared__ __align__(128) char smem_raw[];
    char* smem_al = (char*)(((uintptr_t)smem_raw + 127) & ~(uintptr_t)127);
    const uint32_t sb = smem_u32(smem_al);

    const int tid = threadIdx.x;
    const int l   = tid & 31;
    const int wid = tid >> 5;
    const int wm  = wid >> 2;       // 0..1 -> M offset wm*64
    const int wn  = wid & 3;        // 0..3 -> N offset wn*32

    const int n0 = blockIdx.x * NTILE;     // 0 or 128
    const int m0 = blockIdx.y * MTILE;
    const __half* Abase = Ag + (size_t)m0 * KTOT;
    const __half* Bbase = Bg + (size_t)n0 * KTOT;

    float acc[4][4][4];
#pragma unroll
    for (int a = 0; a < 4; a++)
#pragma unroll
        for (int b = 0; b < 4; b++)
#pragma unroll
            for (int e = 0; e < 4; e++) acc[a][b][e] = 0.0f;

    const uint32_t lrow = (uint32_t)(l & 15);
    const uint32_t lcol = (uint32_t)((l >> 4) * 16);

    load_chunk(sb + A0_OFF, sb + B0_OFF, tid, Abase, Bbase, 0);
    cp_commit();

    for (int kc = 0; kc < NCHUNK; kc++) {
        const int s = kc & 1;
        if (kc + 1 < NCHUNK) {
            load_chunk(sb + (s ? A0_OFF : A1_OFF), sb + (s ? B0_OFF : B1_OFF),
                       tid, Abase, Bbase, kc + 1);
            cp_commit();
            cp_wait<1>();
        } else {
            cp_wait<0>();
        }
        __syncthreads();

        const uint32_t a_s = sb + (s ? A1_OFF : A0_OFF);
        const uint32_t b_s = sb + (s ? B1_OFF : B0_OFF);
#pragma unroll
        for (int ks = 0; ks < 4; ks++) {
            uint32_t af[4][4], bf[2][4];
#pragma unroll
            for (int mt = 0; mt < 4; mt++) {
                uint32_t off = (uint32_t)((wm * 64 + mt * 16 + lrow) * 128 +
                                          ks * 32 + lcol);
                ldm_x4(a_s + sw128(off), af[mt][0], af[mt][1], af[mt][2], af[mt][3]);
            }
#pragma unroll
            for (int bt = 0; bt < 2; bt++) {
                uint32_t off = (uint32_t)((wn * 32 + bt * 16 + lrow) * 128 +
                                          ks * 32 + lcol);
                ldm_x4(b_s + sw128(off), bf[bt][0], bf[bt][1], bf[bt][2], bf[bt][3]);
            }
#pragma unroll
            for (int mt = 0; mt < 4; mt++)
#pragma unroll
                for (int nt = 0; nt < 4; nt++)
                    mma16816(acc[mt][nt], af[mt],
                             bf[nt >> 1][nt & 1], bf[nt >> 1][(nt & 1) + 2]);
        }
        __syncthreads();
    }

    // ---- epilogue: per 32-instance group, smem transpose -> log -> coalesced
    float* fs = (float*)smem_al;                 // 128 x 33 floats = 16.9 KB
    const int bglob = m0 >> 10;                  // batch index (tile within one b)
    const int mrem  = m0 & 1023;
#pragma unroll 1
    for (int g = 0; g < 4; g++) {
        __syncthreads();
        if (wn == g) {
#pragma unroll
            for (int mt = 0; mt < 4; mt++)
#pragma unroll
                for (int nt = 0; nt < 4; nt++)
#pragma unroll
                    for (int e = 0; e < 4; e++) {
                        int row = (l >> 2) + (e >> 1) * 8;
                        int col = (l & 3) * 2 + (e & 1);
                        int ml = wm * 64 + mt * 16 + row;
                        int nl = nt * 8 + col;
                        fs[ml * 33 + nl] = __logf(acc[mt][nt][e]) - LOG_K;
                    }
        }
        __syncthreads();
        const int i_loc = tid >> 3;              // 0..31
        const int mc    = (tid & 7) * 16;        // 0..112
        const int i_glb = n0 + g * 32 + i_loc;
        float* ob = out + ((size_t)bglob << 18) + ((size_t)i_glb << 10) + mrem + mc;
#pragma unroll
        for (int j = 0; j < 4; j++) {
            float4 v;
            v.x = fs[(mc + j * 4 + 0) * 33 + i_loc];
            v.y = fs[(mc + j * 4 + 1) * 33 + i_loc];
            v.z = fs[(mc + j * 4 + 2) * 33 + i_loc];
            v.w = fs[(mc + j * 4 + 3) * 33 + i_loc];
            *reinterpret_cast<float4*>(ob + j * 4) = v;
        }
    }
}

// ---------------------------------------------------------------------------
// launch
// ---------------------------------------------------------------------------
extern "C" void kernel_launch(void* const* d_in, const int* in_sizes, int n_in,
                              void* d_out, int out_size) {
    const float* x    = (const float*)d_in[0];
    const float* offs = (const float*)d_in[1];
    if (n_in >= 2 && in_sizes[0] == NI * KTOT) {  // defensive: swap if order flipped
        const float* t = x; x = offs; offs = t;
    }
    float* out = (float*)d_out;

    __half *Ap = nullptr, *Bp = nullptr;
    cudaGetSymbolAddress((void**)&Ap, g_A);
    cudaGetSymbolAddress((void**)&Bp, g_B);
    cudaFuncSetAttribute(mex_gemm, cudaFuncAttributeMaxDynamicSharedMemorySize,
                         SMEM_BYTES);

    mex_pass0<<<(NI * KTOT + 255) / 256, 256>>>(offs, Bp);
    mex_pass1<<<BB * OH, 256>>>(x, Ap);
    dim3 grid(2, NPIX / MTILE);
    mex_gemm<<<grid, 256, SMEM_BYTES>>>(Ap, Bp, out);
}